// round 1
// baseline (speedup 1.0000x reference)
#include <cuda_runtime.h>
#include <math.h>

#define Lr 1024
#define Br 32
#define Dr 256
#define LAMf 0.2f
#define NR (Lr*Br)

// Scratch (device globals — no allocation allowed)
__device__ float g_norm[2*NR];   // [0,NR): ||x_i||, [NR,2NR): ||y_j||  (row index r = i*Br+b)
__device__ float g_K[NR*5];      // K[i, j=i+d-2], d=0..4
__device__ float g_cos[NR*5];    // cosine sim on band
__device__ float g_S[NR];        // row sums of K
__device__ float g_t[NR];        // t[j] = sum_i K[i,j]/S[i]

// ---------------------------------------------------------------- norms
__global__ void knorm(const float* __restrict__ m1, const float* __restrict__ m2) {
    int w = (blockIdx.x * blockDim.x + threadIdx.x) >> 5;
    int lane = threadIdx.x & 31;
    if (w >= 2*NR) return;
    const float* base = (w < NR) ? (m1 + (size_t)w * Dr) : (m2 + (size_t)(w - NR) * Dr);
    const float4* p = (const float4*)base;
    float4 a = p[lane];
    float4 c = p[lane + 32];
    float s = a.x*a.x + a.y*a.y + a.z*a.z + a.w*a.w
            + c.x*c.x + c.y*c.y + c.z*c.z + c.w*c.w;
    #pragma unroll
    for (int o = 16; o; o >>= 1) s += __shfl_xor_sync(0xffffffffu, s, o);
    if (lane == 0) g_norm[w] = fmaxf(sqrtf(s), 1e-5f);
}

// ---------------------------------------------------------------- band dots -> K, cos, S
__global__ void kband(const float* __restrict__ m1, const float* __restrict__ m2,
                      const int* __restrict__ lengths) {
    int w = (blockIdx.x * blockDim.x + threadIdx.x) >> 5;   // r = i*Br + b
    int lane = threadIdx.x & 31;
    if (w >= NR) return;
    int b = w % Br;
    int i = w / Br;
    int l = lengths[b];
    if (i >= l) {
        if (lane == 0) {
            g_S[w] = 1.0f;
            #pragma unroll
            for (int d = 0; d < 5; d++) { g_K[w*5+d] = 0.0f; g_cos[w*5+d] = 0.0f; }
        }
        return;
    }
    const float4* xp = (const float4*)(m1 + (size_t)w * Dr);
    float4 xa = xp[lane], xb = xp[lane + 32];
    float nx = g_norm[w];
    float S = 0.0f;
    float Ks[5], Cs[5];
    #pragma unroll
    for (int d = 0; d < 5; d++) {
        int j = i + d - 2;
        float Kv = 0.0f, Cv = 0.0f;
        if (j >= 0 && j < l) {
            int rj = j * Br + b;
            const float4* yp = (const float4*)(m2 + (size_t)rj * Dr);
            float4 ya = yp[lane], yb = yp[lane + 32];
            float dot = xa.x*ya.x + xa.y*ya.y + xa.z*ya.z + xa.w*ya.w
                      + xb.x*yb.x + xb.y*yb.y + xb.z*yb.z + xb.w*yb.w;
            #pragma unroll
            for (int o = 16; o; o >>= 1) dot += __shfl_xor_sync(0xffffffffu, dot, o);
            float ny = g_norm[NR + rj];
            Cv = dot / (nx * ny);
            Kv = expf(-LAMf * (1.0f - Cv));   // band interior: no +100 penalty
        }
        Ks[d] = Kv; Cs[d] = Cv; S += Kv;
    }
    if (lane == 0) {
        g_S[w] = S;
        #pragma unroll
        for (int d = 0; d < 5; d++) { g_K[w*5+d] = Ks[d]; g_cos[w*5+d] = Cs[d]; }
    }
}

// ---------------------------------------------------------------- t[j] = sum_i K[i,j]/S[i]
__global__ void kt(const int* __restrict__ lengths) {
    int r = blockIdx.x * blockDim.x + threadIdx.x;
    if (r >= NR) return;
    int b = r % Br;
    int j = r / Br;
    int l = lengths[b];
    float t = 1.0f;
    if (j < l) {
        t = 0.0f;
        #pragma unroll
        for (int dd = 0; dd < 5; dd++) {
            int i = j + dd - 2;
            if (i >= 0 && i < l) {
                int ri = i * Br + b;
                t += g_K[ri*5 + (j - i + 2)] / g_S[ri];
            }
        }
    }
    g_t[r] = t;
}

// ---------------------------------------------------------------- P_norm band scatter
__global__ void kout(const int* __restrict__ lengths, float* __restrict__ out) {
    int r = blockIdx.x * blockDim.x + threadIdx.x;
    if (r >= NR) return;
    int b = r % Br;
    int i = r / Br;
    int l = lengths[b];
    if (i >= l) return;
    float inv = 1.0f / (g_S[r] * g_t[r]);
    float* Po = out + (size_t)b * Lr * Lr + (size_t)i * Lr;
    #pragma unroll
    for (int d = 0; d < 5; d++) {
        int j = i + d - 2;
        if (j >= 0 && j < l) {
            Po[j] = g_K[r*5+d] * g_t[j*Br + b] * inv;
        }
    }
}

// ---------------------------------------------------------------- cost (deterministic per-batch reduce)
__global__ void kcost(const int* __restrict__ lengths, float* __restrict__ out) {
    __shared__ float sh[256];
    int b = blockIdx.x;
    int l = lengths[b];
    float lf = (float)l;
    float acc = 0.0f;
    for (int i = threadIdx.x; i < l; i += 256) {
        int r = i * Br + b;
        float coef = 1.0f / (lf * g_S[r] * g_t[r]);
        float sum = 0.0f;
        #pragma unroll
        for (int d = 0; d < 5; d++) {
            int j = i + d - 2;
            if (j >= 0 && j < l)
                sum += g_K[r*5+d] * (1.0f - g_cos[r*5+d]);
        }
        acc += coef * sum;
    }
    sh[threadIdx.x] = acc;
    __syncthreads();
    #pragma unroll
    for (int s = 128; s; s >>= 1) {
        if (threadIdx.x < s) sh[threadIdx.x] += sh[threadIdx.x + s];
        __syncthreads();
    }
    if (threadIdx.x == 0) out[(size_t)Br * Lr * Lr + b] = sh[0];
}

extern "C" void kernel_launch(void* const* d_in, const int* in_sizes, int n_in,
                              void* d_out, int out_size) {
    const float* m1      = (const float*)d_in[0];
    const float* m2      = (const float*)d_in[1];
    const int*   lengths = (const int*)d_in[2];
    float* out = (float*)d_out;

    // Output P is (near-)zero off the 5-wide band; zero everything, then scatter the band.
    cudaMemsetAsync(d_out, 0, (size_t)out_size * sizeof(float), 0);

    knorm<<<(2*NR)/8, 256>>>(m1, m2);        // 8 warps/block -> 8192 blocks
    kband<<<NR/8, 256>>>(m1, m2, lengths);   // 4096 blocks
    kt<<<NR/256, 256>>>(lengths);            // 128 blocks
    kout<<<NR/256, 256>>>(lengths, out);     // 128 blocks
    kcost<<<Br, 256>>>(lengths, out);        // 32 blocks
}

// round 2
// speedup vs baseline: 1.2930x; 1.2930x over previous
#include <cuda_runtime.h>
#include <math.h>

#define Lr 1024
#define Br 32
#define Dr 256
#define LAMf 0.2f
#define NR (Lr*Br)

// Scratch (device globals — no allocation allowed). Row index r = i*Br + b.
__device__ float g_K[NR*5];      // K[i, j=i+d-2], d=0..4  (exp(-lam*(1-cos)) on band)
__device__ float g_S[NR];        // row sums of K
__device__ float g_E[NR];        // per-row cost numerator: sum_d K*(1-cos)
__device__ float g_t[NR];        // t[j] = sum_i K[i,j]/S[i]

// ---------------------------------------------------------------- band dots (norms fused)
__global__ void kband(const float* __restrict__ m1, const float* __restrict__ m2,
                      const int* __restrict__ lengths) {
    int w = (blockIdx.x * blockDim.x + threadIdx.x) >> 5;   // r = i*Br + b
    int lane = threadIdx.x & 31;
    if (w >= NR) return;
    int b = w & 31;
    int i = w >> 5;
    int l = lengths[b];
    if (i >= l) {
        if (lane == 0) {
            g_S[w] = 1.0f; g_E[w] = 0.0f;
            #pragma unroll
            for (int d = 0; d < 5; d++) g_K[w*5+d] = 0.0f;
        }
        return;
    }
    const float4* xp = (const float4*)(m1 + (size_t)w * Dr);
    float4 xa = xp[lane], xb = xp[lane + 32];
    // ||x|| inline
    float xx = xa.x*xa.x + xa.y*xa.y + xa.z*xa.z + xa.w*xa.w
             + xb.x*xb.x + xb.y*xb.y + xb.z*xb.z + xb.w*xb.w;
    #pragma unroll
    for (int o = 16; o; o >>= 1) xx += __shfl_xor_sync(0xffffffffu, xx, o);
    float nx = fmaxf(sqrtf(xx), 1e-5f);

    float S = 0.0f, E = 0.0f;
    float Ks[5];
    #pragma unroll
    for (int d = 0; d < 5; d++) {
        int j = i + d - 2;
        float Kv = 0.0f;
        if (j >= 0 && j < l) {
            const float4* yp = (const float4*)(m2 + ((size_t)(j*Br + b)) * Dr);
            float4 ya = yp[lane], yb = yp[lane + 32];
            float dot = xa.x*ya.x + xa.y*ya.y + xa.z*ya.z + xa.w*ya.w
                      + xb.x*yb.x + xb.y*yb.y + xb.z*yb.z + xb.w*yb.w;
            float yy  = ya.x*ya.x + ya.y*ya.y + ya.z*ya.z + ya.w*ya.w
                      + yb.x*yb.x + yb.y*yb.y + yb.z*yb.z + yb.w*yb.w;
            #pragma unroll
            for (int o = 16; o; o >>= 1) {
                dot += __shfl_xor_sync(0xffffffffu, dot, o);
                yy  += __shfl_xor_sync(0xffffffffu, yy,  o);
            }
            float ny = fmaxf(sqrtf(yy), 1e-5f);
            float Mv = 1.0f - dot / (nx * ny);      // cosine distance (band: no penalty)
            Kv = expf(-LAMf * Mv);
            E += Kv * Mv;
        }
        Ks[d] = Kv; S += Kv;
    }
    if (lane == 0) {
        g_S[w] = S; g_E[w] = E;
        #pragma unroll
        for (int d = 0; d < 5; d++) g_K[w*5+d] = Ks[d];
    }
}

// ---------------------------------------------------------------- t[j] + cost (fused, block per batch)
__global__ void ktc(const int* __restrict__ lengths, float* __restrict__ out) {
    __shared__ float sh[1024];
    int b = blockIdx.x;
    int j = threadIdx.x;
    int l = lengths[b];
    float term = 0.0f;
    float t = 1.0f;
    if (j < l) {
        t = 0.0f;
        #pragma unroll
        for (int dd = 0; dd < 5; dd++) {
            int i = j + dd - 2;
            if (i >= 0 && i < l) {
                int ri = i*Br + b;
                t += g_K[ri*5 + (4 - dd)] / g_S[ri];   // K index = j-i+2 = 4-dd
            }
        }
        int r = j*Br + b;
        term = g_E[r] / ((float)l * g_S[r] * t);       // cost contribution of row i=j
    }
    g_t[j*Br + b] = t;
    sh[j] = term;
    __syncthreads();
    #pragma unroll
    for (int s = 512; s; s >>= 1) {
        if (j < s) sh[j] += sh[j + s];
        __syncthreads();
    }
    if (j == 0) out[(size_t)Br * Lr * Lr + b] = sh[0];
}

// ---------------------------------------------------------------- full output writer (coalesced, no memset)
__global__ void kwrite(const int* __restrict__ lengths, float4* __restrict__ out) {
    int blk = blockIdx.x;           // = b*1024 + i  (contiguous output rows)
    int b = blk >> 10;
    int i = blk & 1023;
    int tid = threadIdx.x;
    int l = lengths[b];
    float4 v = make_float4(0.f, 0.f, 0.f, 0.f);
    if (i < l) {
        int j0 = tid << 2;
        if (j0 + 3 >= i - 2 && j0 <= i + 2) {          // chunk intersects band
            int r = i*Br + b;
            float inv = 1.0f / (g_S[r] * g_t[r]);
            float* vv = &v.x;
            #pragma unroll
            for (int k = 0; k < 4; k++) {
                int j = j0 + k;
                int d = j - i + 2;
                if (d >= 0 && d < 5 && j < l)
                    vv[k] = g_K[r*5 + d] * g_t[j*Br + b] * inv;
            }
        }
    }
    out[(size_t)blk * 256 + tid] = v;
}

extern "C" void kernel_launch(void* const* d_in, const int* in_sizes, int n_in,
                              void* d_out, int out_size) {
    const float* m1      = (const float*)d_in[0];
    const float* m2      = (const float*)d_in[1];
    const int*   lengths = (const int*)d_in[2];
    float* out = (float*)d_out;

    kband<<<NR/8, 256>>>(m1, m2, lengths);     // 4096 blocks, warp per (i,b)
    ktc<<<Br, 1024>>>(lengths, out);           // t + cost
    kwrite<<<Br*Lr, 256>>>(lengths, (float4*)out);  // full 134MB coalesced write
}

// round 3
// speedup vs baseline: 2.0426x; 1.5797x over previous
#include <cuda_runtime.h>
#include <math.h>

#define Lr 1024
#define Br 32
#define Dr 256
#define LAMf 0.2f
#define NR (Lr*Br)

// Scratch (device globals). Row index r = i*Br + b.
__device__ float g_K[NR*5];      // K[i, j=i+d-2], d=0..4
__device__ float g_S[NR];        // row sums of K
__device__ float g_E[NR];        // per-row cost numerator: sum_d K*(1-cos)

// ---------------------------------------------------------------- fused: zero-fill P + band compute
// grid = 12288 blocks of 256 threads. bid%3==2 -> band block (4096 total, 8 warps = 8 rows each);
// otherwise zero block (8192 total, each thread writes one float4 of zeros).
__global__ void kfused(const float* __restrict__ m1, const float* __restrict__ m2,
                       const int* __restrict__ lengths, float4* __restrict__ out) {
    int bid = blockIdx.x;
    int tid = threadIdx.x;
    int rem = bid % 3;
    if (rem != 2) {
        // ---- zero role: zid in [0, 8192)
        int zid = (bid / 3) * 2 + rem;
        out[(size_t)zid * 256 + tid] = make_float4(0.f, 0.f, 0.f, 0.f);
        return;
    }
    // ---- band role
    int band_id = bid / 3;                        // [0, 4096)
    int w = band_id * 8 + (tid >> 5);             // r = i*Br + b, w in [0, NR)
    int lane = tid & 31;
    int b = w & 31;
    int i = w >> 5;
    int l = __ldg(lengths + b);
    if (i >= l) {
        if (lane == 0) {
            g_S[w] = 1.0f; g_E[w] = 0.0f;
            #pragma unroll
            for (int d = 0; d < 5; d++) g_K[w*5+d] = 0.0f;
        }
        return;
    }
    const float4* xp = (const float4*)(m1 + (size_t)w * Dr);
    float4 xa = xp[lane], xb = xp[lane + 32];
    float xx = xa.x*xa.x + xa.y*xa.y + xa.z*xa.z + xa.w*xa.w
             + xb.x*xb.x + xb.y*xb.y + xb.z*xb.z + xb.w*xb.w;
    #pragma unroll
    for (int o = 16; o; o >>= 1) xx += __shfl_xor_sync(0xffffffffu, xx, o);
    float nx = fmaxf(sqrtf(xx), 1e-5f);

    float S = 0.0f, E = 0.0f;
    float Ks[5];
    #pragma unroll
    for (int d = 0; d < 5; d++) {
        int j = i + d - 2;
        float Kv = 0.0f;
        if (j >= 0 && j < l) {
            const float4* yp = (const float4*)(m2 + ((size_t)(j*Br + b)) * Dr);
            float4 ya = yp[lane], yb = yp[lane + 32];
            float dot = xa.x*ya.x + xa.y*ya.y + xa.z*ya.z + xa.w*ya.w
                      + xb.x*yb.x + xb.y*yb.y + xb.z*yb.z + xb.w*yb.w;
            float yy  = ya.x*ya.x + ya.y*ya.y + ya.z*ya.z + ya.w*ya.w
                      + yb.x*yb.x + yb.y*yb.y + yb.z*yb.z + yb.w*yb.w;
            #pragma unroll
            for (int o = 16; o; o >>= 1) {
                dot += __shfl_xor_sync(0xffffffffu, dot, o);
                yy  += __shfl_xor_sync(0xffffffffu, yy,  o);
            }
            float ny = fmaxf(sqrtf(yy), 1e-5f);
            float Mv = 1.0f - dot / (nx * ny);
            Kv = expf(-LAMf * Mv);
            E += Kv * Mv;
        }
        Ks[d] = Kv; S += Kv;
    }
    if (lane == 0) {
        g_S[w] = S; g_E[w] = E;
        #pragma unroll
        for (int d = 0; d < 5; d++) g_K[w*5+d] = Ks[d];
    }
}

// ---------------------------------------------------------------- t + cost + band scatter (block per batch)
__global__ void ktc(const int* __restrict__ lengths, float* __restrict__ out) {
    __shared__ float sh_t[Lr];
    __shared__ float sh_c[Lr];
    int b = blockIdx.x;
    int j = threadIdx.x;
    int l = lengths[b];

    float t = 1.0f, term = 0.0f;
    if (j < l) {
        t = 0.0f;
        #pragma unroll
        for (int dd = 0; dd < 5; dd++) {
            int i = j + dd - 2;
            if (i >= 0 && i < l) {
                int ri = i*Br + b;
                t += g_K[ri*5 + (4 - dd)] / g_S[ri];   // K index = j-i+2 = 4-dd
            }
        }
        int r = j*Br + b;
        term = g_E[r] / ((float)l * g_S[r] * t);
    }
    sh_t[j] = t;
    sh_c[j] = term;
    __syncthreads();

    // band scatter: thread j writes output row i=j
    if (j < l) {
        int r = j*Br + b;
        float inv = 1.0f / (g_S[r] * sh_t[j]);
        float* Po = out + (size_t)b * Lr * Lr + (size_t)j * Lr;
        #pragma unroll
        for (int d = 0; d < 5; d++) {
            int jj = j + d - 2;
            if (jj >= 0 && jj < l)
                Po[jj] = g_K[r*5+d] * sh_t[jj] * inv;
        }
    }

    // cost reduction
    #pragma unroll
    for (int s = 512; s; s >>= 1) {
        if (j < s) sh_c[j] += sh_c[j + s];
        __syncthreads();
    }
    if (j == 0) out[(size_t)Br * Lr * Lr + b] = sh_c[0];
}

extern "C" void kernel_launch(void* const* d_in, const int* in_sizes, int n_in,
                              void* d_out, int out_size) {
    const float* m1      = (const float*)d_in[0];
    const float* m2      = (const float*)d_in[1];
    const int*   lengths = (const int*)d_in[2];
    float* out = (float*)d_out;

    kfused<<<12288, 256>>>(m1, m2, lengths, (float4*)out);  // zero P + band math, overlapped
    ktc<<<Br, 1024>>>(lengths, out);                        // t + cost + band scatter
}

// round 4
// speedup vs baseline: 2.6529x; 1.2988x over previous
#include <cuda_runtime.h>
#include <math.h>

#define Lr 1024
#define Br 32
#define Dr 256
#define LAMf 0.2f
#define NR (Lr*Br)

// Scratch (device globals). BATCH-MAJOR row index r = b*Lr + i.
__device__ float g_K[NR*5];      // K[i, j=i+d-2], d=0..4
__device__ float g_S[NR];        // row sums of K
__device__ float g_E[NR];        // per-row cost numerator: sum_d K*(1-cos)

// ---------------------------------------------------------------- fused: zero-fill P + band compute
// grid = 12288 blocks of 256 threads. bid%3==2 -> band block (4096, 8 warps = 8 rows each);
// otherwise zero block (8192, each thread writes one float4 of zeros).
__global__ void kfused(const float* __restrict__ m1, const float* __restrict__ m2,
                       const int* __restrict__ lengths, float4* __restrict__ out) {
    int bid = blockIdx.x;
    int tid = threadIdx.x;
    int rem = bid % 3;
    if (rem != 2) {
        int zid = (bid / 3) * 2 + rem;                 // [0, 8192)
        out[(size_t)zid * 256 + tid] = make_float4(0.f, 0.f, 0.f, 0.f);
        return;
    }
    int w = (bid / 3) * 8 + (tid >> 5);                // w in [0, NR): input row (i,b)
    int lane = tid & 31;
    int b = w & 31;
    int i = w >> 5;
    int rr = b * Lr + i;                               // batch-major scratch index
    int l = __ldg(lengths + b);
    if (i >= l) {
        if (lane == 0) {
            g_S[rr] = 1.0f; g_E[rr] = 0.0f;
            #pragma unroll
            for (int d = 0; d < 5; d++) g_K[rr*5+d] = 0.0f;
        }
        return;
    }
    const float4* xp = (const float4*)(m1 + (size_t)w * Dr);
    float4 xa = xp[lane], xb = xp[lane + 32];
    float xx = xa.x*xa.x + xa.y*xa.y + xa.z*xa.z + xa.w*xa.w
             + xb.x*xb.x + xb.y*xb.y + xb.z*xb.z + xb.w*xb.w;
    #pragma unroll
    for (int o = 16; o; o >>= 1) xx += __shfl_xor_sync(0xffffffffu, xx, o);
    float nx = fmaxf(sqrtf(xx), 1e-5f);

    float S = 0.0f, E = 0.0f;
    float Ks[5];
    #pragma unroll
    for (int d = 0; d < 5; d++) {
        int j = i + d - 2;
        float Kv = 0.0f;
        if (j >= 0 && j < l) {
            const float4* yp = (const float4*)(m2 + ((size_t)(j*Br + b)) * Dr);
            float4 ya = yp[lane], yb = yp[lane + 32];
            float dot = xa.x*ya.x + xa.y*ya.y + xa.z*ya.z + xa.w*ya.w
                      + xb.x*yb.x + xb.y*yb.y + xb.z*yb.z + xb.w*yb.w;
            float yy  = ya.x*ya.x + ya.y*ya.y + ya.z*ya.z + ya.w*ya.w
                      + yb.x*yb.x + yb.y*yb.y + yb.z*yb.z + yb.w*yb.w;
            #pragma unroll
            for (int o = 16; o; o >>= 1) {
                dot += __shfl_xor_sync(0xffffffffu, dot, o);
                yy  += __shfl_xor_sync(0xffffffffu, yy,  o);
            }
            float ny = fmaxf(sqrtf(yy), 1e-5f);
            float Mv = 1.0f - dot / (nx * ny);
            Kv = expf(-LAMf * Mv);
            E += Kv * Mv;
        }
        Ks[d] = Kv; S += Kv;
    }
    if (lane == 0) {
        g_S[rr] = S; g_E[rr] = E;
        #pragma unroll
        for (int d = 0; d < 5; d++) g_K[rr*5+d] = Ks[d];
    }
}

// ---------------------------------------------------------------- t + cost + band scatter (block per batch)
// All per-batch scratch (28 KB) staged into smem via coalesced loads; gathers hit LDS.
__global__ void ktc(const int* __restrict__ lengths, float* __restrict__ out) {
    __shared__ float sh_K[Lr*5];
    __shared__ float sh_S[Lr];
    __shared__ float sh_E[Lr];
    __shared__ float sh_t[Lr];
    __shared__ float sh_c[Lr];
    int b = blockIdx.x;
    int j = threadIdx.x;
    int l = lengths[b];
    int base = b * Lr;

    // coalesced staging: 5 float4 chunks of K + 1 of S + 1 of E per thread... do flat float4
    {
        const float4* Ksrc = (const float4*)(g_K + (size_t)base * 5);
        float4* Kdst = (float4*)sh_K;
        #pragma unroll
        for (int k = 0; k < 2; k++)          // 1024 threads * 2 = 2048 float4 > 1280 needed
            if (j + k*1024 < Lr*5/4) Kdst[j + k*1024] = Ksrc[j + k*1024];
        if (j < Lr/4) {
            ((float4*)sh_S)[j] = ((const float4*)(g_S + base))[j];
            ((float4*)sh_E)[j] = ((const float4*)(g_E + base))[j];
        }
    }
    __syncthreads();

    float t = 1.0f, term = 0.0f;
    if (j < l) {
        t = 0.0f;
        #pragma unroll
        for (int dd = 0; dd < 5; dd++) {
            int i = j + dd - 2;
            if (i >= 0 && i < l)
                t += sh_K[i*5 + (4 - dd)] / sh_S[i];   // d = j-i+2 = 4-dd
        }
        term = sh_E[j] / ((float)l * sh_S[j] * t);
    }
    sh_t[j] = t;
    sh_c[j] = term;
    __syncthreads();

    // band scatter: thread j writes output row i=j
    if (j < l) {
        float inv = 1.0f / (sh_S[j] * sh_t[j]);
        float* Po = out + (size_t)b * Lr * Lr + (size_t)j * Lr;
        #pragma unroll
        for (int d = 0; d < 5; d++) {
            int jj = j + d - 2;
            if (jj >= 0 && jj < l)
                Po[jj] = sh_K[j*5+d] * sh_t[jj] * inv;
        }
    }

    // cost reduction
    #pragma unroll
    for (int s = 512; s; s >>= 1) {
        if (j < s) sh_c[j] += sh_c[j + s];
        __syncthreads();
    }
    if (j == 0) out[(size_t)Br * Lr * Lr + b] = sh_c[0];
}

extern "C" void kernel_launch(void* const* d_in, const int* in_sizes, int n_in,
                              void* d_out, int out_size) {
    const float* m1      = (const float*)d_in[0];
    const float* m2      = (const float*)d_in[1];
    const int*   lengths = (const int*)d_in[2];
    float* out = (float*)d_out;

    kfused<<<12288, 256>>>(m1, m2, lengths, (float4*)out);  // zero P + band math, overlapped
    ktc<<<Br, 1024>>>(lengths, out);                        // t + cost + band scatter (smem-staged)
}